// round 14
// baseline (speedup 1.0000x reference)
#include <cuda_runtime.h>
#include <cuda_bf16.h>
#include <cuda_fp16.h>
#include <math.h>
#include <stdint.h>

#define S_FR   8
#define BATCH  2
#define CKD    64
#define HW     4096
#define SHW    32768
#define RADIUS 0.1f
#define WEIGHTC (0.2f / (8.0f * 64.0f * 64.0f))
#define LOG2E   1.4426950408889634f
#define TPB    256          // prepass blocks
#define ATPB   512          // attention kernel: 16 warps
#define NT     256          // KV tiles per CTA (16384 keys / 64)
#define STG    16384        // stage: KH 8K | VH 8K
#define NBUF   6
#define SMEM_TOTAL (NBUF * STG)   // 98304

// ---- device scratch ----
__device__ __half g_Kh  [(size_t)BATCH*SHW*CKD];   // [b][kv][c] fp16
__device__ __half g_Vh  [(size_t)BATCH*CKD*SHW];   // [b][c][kv] fp16
__device__ __half g_Qt_hi[(size_t)BATCH*HW*CKD];   // [b][q][c] fp16 (x log2e)
__device__ __half g_Qt_lo[(size_t)BATCH*HW*CKD];   // fp16 residual
__device__ float g_Opart[4][(size_t)BATCH*HW*CKD];
__device__ float g_Lpart[4][(size_t)BATCH*HW];
__device__ float g_Mpart[4][(size_t)BATCH*HW];
__device__ float g_maskV[BATCH][CKD];

// ---- helpers ----
__device__ __forceinline__ uint32_t smem_u32(const void* p) {
    uint32_t a;
    asm("{ .reg .u64 t; cvta.to.shared.u64 t, %1; cvt.u32.u64 %0, t; }" : "=r"(a) : "l"(p));
    return a;
}
__device__ __forceinline__ uint32_t cvt2_f16(float lo, float hi) {
    uint32_t r;
    asm("cvt.rn.f16x2.f32 %0, %1, %2;" : "=r"(r) : "f"(hi), "f"(lo));
    return r;
}
__device__ __forceinline__ uint32_t ex2_f16x2(uint32_t x) {
    uint32_t r;
    asm("ex2.approx.f16x2 %0, %1;" : "=r"(r) : "r"(x));
    return r;
}
__device__ __forceinline__ void unpack_f16(uint32_t h, float& x, float& y) {
    asm("{.reg .f16 a,b; mov.b32 {a,b}, %2; cvt.f32.f16 %0, a; cvt.f32.f16 %1, b;}"
        : "=f"(x), "=f"(y) : "r"(h));
}
__device__ __forceinline__ float ex2f(float x) {
    float r; asm("ex2.approx.ftz.f32 %0, %1;" : "=f"(r) : "f"(x)); return r;
}
__device__ __forceinline__ void split2h(float x0, float x1, uint32_t& h, uint32_t& l) {
    h = cvt2_f16(x0, x1);
    float a0, a1;
    unpack_f16(h, a0, a1);
    l = cvt2_f16(x0 - a0, x1 - a1);
}

#define LDSM4(r, a) \
    asm volatile("ldmatrix.sync.aligned.m8n8.x4.shared.b16 {%0,%1,%2,%3}, [%4];" \
        : "=r"((r)[0]), "=r"((r)[1]), "=r"((r)[2]), "=r"((r)[3]) : "r"(a))

#define MMAH(c, a, b0, b1) \
    asm volatile("mma.sync.aligned.m16n8k16.row.col.f32.f16.f16.f32 " \
        "{%0,%1,%2,%3}, {%4,%5,%6,%7}, {%8,%9}, {%0,%1,%2,%3};" \
        : "+f"((c)[0]), "+f"((c)[1]), "+f"((c)[2]), "+f"((c)[3]) \
        : "r"((a)[0]), "r"((a)[1]), "r"((a)[2]), "r"((a)[3]), "r"(b0), "r"(b1))

#define CPA16(dst, src) \
    asm volatile("cp.async.cg.shared.global [%0], [%1], 16;" :: "r"(dst), "l"(src))

// ---- prepass: merged K/Q transpose (fp16) ----
__global__ void kqtrans_kernel(const float* __restrict__ mk,
                               const float* __restrict__ qq) {
    __shared__ float st[128][65];
    int blk = blockIdx.x;
    int tid = threadIdx.x;
    if (blk == 0 && tid < BATCH * CKD) ((float*)g_maskV)[tid] = 0.f;

    const float* src;
    size_t ob;
    float scale;
    bool isq = (blk >= 512);
    if (!isq) {
        int hwt = blk & 31, b = (blk >> 5) & 1, s = blk >> 6;
        int hw0 = hwt * 128;
        src = mk + (((size_t)s * BATCH + b) * CKD) * HW + hw0;
        ob = ((size_t)b * SHW + (size_t)s * HW + hw0) * CKD;
        scale = 1.0f;
    } else {
        int q = blk - 512;
        int hwt = q & 31, b = q >> 5;
        int hw0 = hwt * 128;
        src = qq + ((size_t)b * CKD) * HW + hw0;
        ob = ((size_t)b * HW + hw0) * CKD;
        scale = LOG2E;
    }
    for (int i = tid; i < 2048; i += TPB) {
        int c = i >> 5, j4 = (i & 31) * 4;
        float4 v = *(const float4*)(src + (size_t)c * HW + j4);
        st[j4][c] = v.x * scale; st[j4+1][c] = v.y * scale;
        st[j4+2][c] = v.z * scale; st[j4+3][c] = v.w * scale;
    }
    __syncthreads();
    for (int i = tid; i < 1024; i += TPB) {
        int r = i >> 3, c0 = (i & 7) * 8;
        uint32_t h4[4], l4[4];
        #pragma unroll
        for (int k = 0; k < 4; k++) split2h(st[r][c0+2*k], st[r][c0+2*k+1], h4[k], l4[k]);
        if (!isq) {
            *(uint4*)(g_Kh + ob + (size_t)r * CKD + c0) = *(uint4*)h4;
        } else {
            *(uint4*)(g_Qt_hi + ob + (size_t)r * CKD + c0) = *(uint4*)h4;
            *(uint4*)(g_Qt_lo + ob + (size_t)r * CKD + c0) = *(uint4*)l4;
        }
    }
}

// V convert fp16 + fused maskV reduction
__global__ void vconv_kernel(const float* __restrict__ mv,
                             const float* __restrict__ disp,
                             const int* __restrict__ seq) {
    __shared__ float red[8];
    int tid = threadIdx.x;
    size_t i = (size_t)blockIdx.x * TPB + tid;
    size_t e4 = i * 4;
    int hw = (int)(e4 & 4095);
    size_t t = e4 >> 12;
    int c = (int)(t & 63); t >>= 6;
    int b = (int)(t & 1);  int s = (int)(t >> 1);
    float4 v = *(const float4*)(mv + e4);
    size_t o = (((size_t)b * CKD + c) * SHW) + (size_t)s * HW + hw;
    uint2 hh;
    hh.x = cvt2_f16(v.x, v.y);
    hh.y = cvt2_f16(v.z, v.w);
    *(uint2*)(g_Vh + o) = hh;

    float d0 = (float)seq[(b * S_FR + s) * 2 + 0] - 5.0f;
    float d1 = (float)seq[(b * S_FR + s) * 2 + 1] - 5.0f;
    float dist = sqrtf(d1 * d1 + d0 * d0);
    const float* dp = disp + (size_t)b * HW + hw;
    float a = 0.f;
    if (fabsf(dist * dp[0]) > RADIUS) a += v.x;
    if (fabsf(dist * dp[1]) > RADIUS) a += v.y;
    if (fabsf(dist * dp[2]) > RADIUS) a += v.z;
    if (fabsf(dist * dp[3]) > RADIUS) a += v.w;
    #pragma unroll
    for (int off = 16; off; off >>= 1) a += __shfl_xor_sync(0xffffffffu, a, off);
    if ((tid & 31) == 0) red[tid >> 5] = a;
    __syncthreads();
    if (tid == 0) {
        float tot = 0.f;
        #pragma unroll
        for (int w = 0; w < 8; w++) tot += red[w];
        atomicAdd(&g_maskV[b][c], tot * WEIGHTC);
    }
}

// ---- main attention kernel: software-pipelined (PV(t) || QK(t+1)) ----
struct WarpCtx {
    uint32_t qh[4][4], ql[4][4];
    float o[8][4];
    float lacc[2];
    float mrow[2];
    uint32_t lro, lcb_lsw16[4];   // precomputed coff per k index not used; keep simple
    int lcb, lsw;
    int nw;
    uint32_t sb;
};

__global__ __launch_bounds__(ATPB, 1) void attn_mma_kernel() {
    extern __shared__ char smem[];
    uint32_t sb = smem_u32(smem);
    int tid = threadIdx.x, wid = tid >> 5, L = tid & 31;
    int blk = blockIdx.x;                 // 128
    int h  = blk & 1;
    int qt = (blk >> 1) & 31;
    int b  = blk >> 6;
    int q0 = qt * 128;
    int kv0 = h * 16384;
    int mw = wid & 7;      // M group (16 rows)
    int nw = wid >> 3;     // key half

    // ---- Q fragments straight from gmem (A-frag layout, m16, fp16 hi/lo) ----
    uint32_t qh[4][4], ql[4][4];
    {
        const __half* QbH = g_Qt_hi + ((size_t)b * HW + q0) * CKD;
        const __half* QbL = g_Qt_lo + ((size_t)b * HW + q0) * CKD;
        int r = mw * 16 + (L >> 2);
        #pragma unroll
        for (int k = 0; k < 4; k++) {
            int cc = 2 * (L & 3) + 16 * k;
            qh[k][0] = *(const uint32_t*)(QbH + (size_t)r * CKD + cc);
            qh[k][1] = *(const uint32_t*)(QbH + (size_t)(r + 8) * CKD + cc);
            qh[k][2] = *(const uint32_t*)(QbH + (size_t)r * CKD + cc + 8);
            qh[k][3] = *(const uint32_t*)(QbH + (size_t)(r + 8) * CKD + cc + 8);
            ql[k][0] = *(const uint32_t*)(QbL + (size_t)r * CKD + cc);
            ql[k][1] = *(const uint32_t*)(QbL + (size_t)(r + 8) * CKD + cc);
            ql[k][2] = *(const uint32_t*)(QbL + (size_t)r * CKD + cc + 8);
            ql[k][3] = *(const uint32_t*)(QbL + (size_t)(r + 8) * CKD + cc + 8);
        }
    }

    const __half* KH = g_Kh + ((size_t)b * SHW + kv0) * CKD;
    const __half* VH = g_Vh + (size_t)b * CKD * SHW + kv0;

    int r0 = tid >> 3, c0 = tid & 7;
    uint32_t so0 = (uint32_t)(r0 * 128 + ((c0 ^ (r0 & 7)) * 16));

    int lrow = (L & 7) + ((L & 16) >> 1);
    int lcb  = (L >> 3) & 1;
    uint32_t lro = (uint32_t)lrow * 128;
    int lsw = lrow & 7;

#define LOAD_TILE(tt, bufidx) do { \
    uint32_t bb = sb + (uint32_t)(bufidx) * STG; \
    size_t kvo = (size_t)(tt) * 64; \
    CPA16(bb + so0,        KH + (kvo + r0) * CKD + c0 * 8); \
    CPA16(bb + 8192 + so0, VH + (size_t)r0 * SHW + kvo + c0 * 8); \
    asm volatile("cp.async.commit_group;"); \
} while (0)

    LOAD_TILE(0, 0);
    LOAD_TILE(1, 1);
    LOAD_TILE(2, 2);
    LOAD_TILE(3, 3);

    float o[8][4];
    #pragma unroll
    for (int i = 0; i < 8; i++) o[i][0] = o[i][1] = o[i][2] = o[i][3] = 0.f;
    float lacc[2] = {0.f, 0.f};
    float mrow[2] = {-1e30f, -1e30f};
    float cA[4][4], cB[4][4];

    asm volatile("cp.async.wait_group 0;");
    __syncthreads();

    // ---- prologue: QK(0) -> cA ----
    {
        uint32_t kb = sb;   // tile 0, buf 0
        #pragma unroll
        for (int i = 0; i < 4; i++) cA[i][0] = cA[i][1] = cA[i][2] = cA[i][3] = 0.f;
        #pragma unroll
        for (int k = 0; k < 4; k++) {
            uint32_t coff = (uint32_t)(((2 * k + lcb) ^ lsw) * 16);
            uint32_t base0 = kb + (uint32_t)(nw * 2 + 0) * 2048 + lro;
            uint32_t base1 = kb + (uint32_t)(nw * 2 + 1) * 2048 + lro;
            uint32_t bh0[4], bh1[4];
            LDSM4(bh0, base0 + coff);
            LDSM4(bh1, base1 + coff);
            MMAH(cA[0], qh[k], bh0[0], bh0[1]);
            MMAH(cA[2], qh[k], bh1[0], bh1[1]);
            MMAH(cA[1], qh[k], bh0[2], bh0[3]);
            MMAH(cA[3], qh[k], bh1[2], bh1[3]);
            MMAH(cA[0], ql[k], bh0[0], bh0[1]);
            MMAH(cA[2], ql[k], bh1[0], bh1[1]);
            MMAH(cA[1], ql[k], bh0[2], bh0[3]);
            MMAH(cA[3], ql[k], bh1[2], bh1[3]);
        }
    }

    // body for one tile t: softmax(c_cur) -> P; then interleaved PV(t) + QK(t+1)->c_nxt
#define TILE_BODY(t, c_cur, c_nxt) do { \
    /* online row max (base-2), lazy rescale */ \
    { \
        float a0 = fmaxf(fmaxf(c_cur[0][0], c_cur[0][1]), fmaxf(c_cur[1][0], c_cur[1][1])); \
        a0 = fmaxf(a0, fmaxf(fmaxf(c_cur[2][0], c_cur[2][1]), fmaxf(c_cur[3][0], c_cur[3][1]))); \
        float a1 = fmaxf(fmaxf(c_cur[0][2], c_cur[0][3]), fmaxf(c_cur[1][2], c_cur[1][3])); \
        a1 = fmaxf(a1, fmaxf(fmaxf(c_cur[2][2], c_cur[2][3]), fmaxf(c_cur[3][2], c_cur[3][3]))); \
        a0 = fmaxf(a0, __shfl_xor_sync(0xffffffffu, a0, 1)); \
        a0 = fmaxf(a0, __shfl_xor_sync(0xffffffffu, a0, 2)); \
        a1 = fmaxf(a1, __shfl_xor_sync(0xffffffffu, a1, 1)); \
        a1 = fmaxf(a1, __shfl_xor_sync(0xffffffffu, a1, 2)); \
        if (a0 > mrow[0]) { \
            float sc = ex2f(mrow[0] - a0); \
            lacc[0] *= sc; \
            _Pragma("unroll") \
            for (int vt = 0; vt < 8; vt++) { o[vt][0] *= sc; o[vt][1] *= sc; } \
            mrow[0] = a0; \
        } \
        if (a1 > mrow[1]) { \
            float sc = ex2f(mrow[1] - a1); \
            lacc[1] *= sc; \
            _Pragma("unroll") \
            for (int vt = 0; vt < 8; vt++) { o[vt][2] *= sc; o[vt][3] *= sc; } \
            mrow[1] = a1; \
        } \
    } \
    uint32_t ph[8]; \
    _Pragma("unroll") \
    for (int jt = 0; jt < 4; jt++) { \
        int base = (jt >> 1) * 4 + (jt & 1) * 2; \
        uint32_t d0 = cvt2_f16(c_cur[jt][0] - mrow[0], c_cur[jt][1] - mrow[0]); \
        uint32_t d1 = cvt2_f16(c_cur[jt][2] - mrow[1], c_cur[jt][3] - mrow[1]); \
        uint32_t p0 = ex2_f16x2(d0); \
        uint32_t p1 = ex2_f16x2(d1); \
        ph[base]     = p0; \
        ph[base + 1] = p1; \
        float f0, f1, f2, f3; \
        unpack_f16(p0, f0, f1); \
        unpack_f16(p1, f2, f3); \
        lacc[0] += f0 + f1; \
        lacc[1] += f2 + f3; \
    } \
    /* interleaved PV(t) + QK(t+1) */ \
    { \
        uint32_t kbV = sb + (uint32_t)((t) % NBUF) * STG; \
        uint32_t kbK = sb + (uint32_t)(((t) + 1) % NBUF) * STG; \
        bool doqk = ((t) + 1 < NT); \
        _Pragma("unroll") \
        for (int i = 0; i < 4; i++) c_nxt[i][0] = c_nxt[i][1] = c_nxt[i][2] = c_nxt[i][3] = 0.f; \
        _Pragma("unroll") \
        for (int kk = 0; kk < 4; kk++) { \
            int jl = kk >> 1, np = kk & 1; \
            int jg = nw * 2 + jl; \
            uint32_t coffV = (uint32_t)(((2 * jg + lcb) ^ lsw) * 16); \
            uint32_t va[4], vb[4]; \
            LDSM4(va, kbV + 8192 + (uint32_t)(2 * np) * 2048 + lro + coffV); \
            LDSM4(vb, kbV + 8192 + (uint32_t)(2 * np + 1) * 2048 + lro + coffV); \
            uint32_t* Ah = ph + jl * 4; \
            if (doqk) { \
                uint32_t coffK = (uint32_t)(((2 * kk + lcb) ^ lsw) * 16); \
                uint32_t bh0[4], bh1[4]; \
                LDSM4(bh0, kbK + (uint32_t)(nw * 2 + 0) * 2048 + lro + coffK); \
                LDSM4(bh1, kbK + (uint32_t)(nw * 2 + 1) * 2048 + lro + coffK); \
                MMAH(c_nxt[0], qh[kk], bh0[0], bh0[1]); \
                MMAH(o[4*np],     Ah, va[0], va[1]); \
                MMAH(c_nxt[2], qh[kk], bh1[0], bh1[1]); \
                MMAH(o[4*np + 2], Ah, vb[0], vb[1]); \
                MMAH(c_nxt[1], qh[kk], bh0[2], bh0[3]); \
                MMAH(o[4*np + 1], Ah, va[2], va[3]); \
                MMAH(c_nxt[3], qh[kk], bh1[2], bh1[3]); \
                MMAH(o[4*np + 3], Ah, vb[2], vb[3]); \
                MMAH(c_nxt[0], ql[kk], bh0[0], bh0[1]); \
                MMAH(c_nxt[2], ql[kk], bh1[0], bh1[1]); \
                MMAH(c_nxt[1], ql[kk], bh0[2], bh0[3]); \
                MMAH(c_nxt[3], ql[kk], bh1[2], bh1[3]); \
            } else { \
                MMAH(o[4*np],     Ah, va[0], va[1]); \
                MMAH(o[4*np + 2], Ah, vb[0], vb[1]); \
                MMAH(o[4*np + 1], Ah, va[2], va[3]); \
                MMAH(o[4*np + 3], Ah, vb[2], vb[3]); \
            } \
        } \
    } \
} while (0)

    for (int tt = 0; tt < NT; tt += 2) {
        if (tt > 0) {
            asm volatile("cp.async.wait_group 0;");
            __syncthreads();
        }
        if (tt + 4 < NT) LOAD_TILE(tt + 4, (tt + 4) % NBUF);
        if (tt + 5 < NT) LOAD_TILE(tt + 5, (tt + 5) % NBUF);

        TILE_BODY(tt,     cA, cB);
        TILE_BODY(tt + 1, cB, cA);
    }

    // ---- epilogue: store partials (slot = h*2 + nw) ----
    int slot = h * 2 + nw;
    {
        float l0 = lacc[0], l1 = lacc[1];
        l0 += __shfl_xor_sync(0xffffffffu, l0, 1);
        l0 += __shfl_xor_sync(0xffffffffu, l0, 2);
        l1 += __shfl_xor_sync(0xffffffffu, l1, 1);
        l1 += __shfl_xor_sync(0xffffffffu, l1, 2);
        int mg = q0 + mw * 16 + (L >> 2);
        float* op = g_Opart[slot] + ((size_t)b * HW + mg) * CKD;
        #pragma unroll
        for (int vt = 0; vt < 8; vt++) {
            int v = vt * 8 + (L & 3) * 2;
            *(float2*)(op + v)           = make_float2(o[vt][0], o[vt][1]);
            *(float2*)(op + 8 * CKD + v) = make_float2(o[vt][2], o[vt][3]);
        }
        if ((L & 3) == 0) {
            g_Lpart[slot][(size_t)b * HW + mg]     = l0;
            g_Lpart[slot][(size_t)b * HW + mg + 8] = l1;
            g_Mpart[slot][(size_t)b * HW + mg]     = mrow[0];
            g_Mpart[slot][(size_t)b * HW + mg + 8] = mrow[1];
        }
    }
}

// ---- combine: FA split-k merge, 512 blocks x 16 rows ----
__global__ void combine_kernel(float* __restrict__ out) {
    __shared__ float st[16][65];
    int g0 = blockIdx.x * 16;
    int tid = threadIdx.x;
    int b = g0 >> 12;
    {
        int r = tid >> 4, v4 = (tid & 15) * 4;
        int row = g0 + r;
        float m0 = g_Mpart[0][row], m1 = g_Mpart[1][row];
        float m2 = g_Mpart[2][row], m3 = g_Mpart[3][row];
        float ms = fmaxf(fmaxf(m0, m1), fmaxf(m2, m3));
        float w0 = ex2f(m0 - ms), w1 = ex2f(m1 - ms);
        float w2 = ex2f(m2 - ms), w3 = ex2f(m3 - ms);
        float lsum = w0 * g_Lpart[0][row] + w1 * g_Lpart[1][row]
                   + w2 * g_Lpart[2][row] + w3 * g_Lpart[3][row];
        float inv = 1.0f / lsum;
        size_t idx = (size_t)row * CKD + v4;
        float4 a0 = *(const float4*)(g_Opart[0] + idx);
        float4 a1 = *(const float4*)(g_Opart[1] + idx);
        float4 a2 = *(const float4*)(g_Opart[2] + idx);
        float4 a3 = *(const float4*)(g_Opart[3] + idx);
        st[r][v4]   = (w0*a0.x + w1*a1.x + w2*a2.x + w3*a3.x) * inv;
        st[r][v4+1] = (w0*a0.y + w1*a1.y + w2*a2.y + w3*a3.y) * inv;
        st[r][v4+2] = (w0*a0.z + w1*a1.z + w2*a2.z + w3*a3.z) * inv;
        st[r][v4+3] = (w0*a0.w + w1*a1.w + w2*a2.w + w3*a3.w) * inv;
    }
    __syncthreads();
    float* ob = out + (size_t)b * CKD * HW;
    int qb = g0 & 4095;
    {
        int v = tid >> 2, r4 = (tid & 3) * 4;
        float mval = g_maskV[b][v];
        float4 w;
        w.x = st[r4][v]   + mval;
        w.y = st[r4+1][v] + mval;
        w.z = st[r4+2][v] + mval;
        w.w = st[r4+3][v] + mval;
        *(float4*)(ob + (size_t)v * HW + qb + r4) = w;
    }
}

// ---- launch ----
extern "C" void kernel_launch(void* const* d_in, const int* in_sizes, int n_in,
                              void* d_out, int out_size) {
    const float* mk   = (const float*)d_in[0];
    const float* mv   = (const float*)d_in[1];
    const float* qq   = (const float*)d_in[2];
    const float* disp = (const float*)d_in[3];
    const int*   seq  = (const int*)d_in[4];
    float* out = (float*)d_out;

    kqtrans_kernel<<<576, TPB>>>(mk, qq);
    vconv_kernel<<<4096, TPB>>>(mv, disp, seq);

    cudaFuncSetAttribute(attn_mma_kernel, cudaFuncAttributeMaxDynamicSharedMemorySize, SMEM_TOTAL);
    attn_mma_kernel<<<128, ATPB, SMEM_TOTAL>>>();

    combine_kernel<<<512, TPB>>>(out);
}

// round 15
// speedup vs baseline: 1.0471x; 1.0471x over previous
#include <cuda_runtime.h>
#include <cuda_bf16.h>
#include <cuda_fp16.h>
#include <math.h>
#include <stdint.h>

#define S_FR   8
#define BATCH  2
#define CKD    64
#define HW     4096
#define SHW    32768
#define RADIUS 0.1f
#define WEIGHTC (0.2f / (8.0f * 64.0f * 64.0f))
#define LOG2E   1.4426950408889634f
#define TPB    256          // prepass blocks
#define ATPB   512          // attention kernel: 16 warps
#define NT     256          // KV tiles per CTA (16384 keys / 64)
#define STG    16384        // stage: KH 8K | VH 8K
#define NBUF   6
#define SMEM_TOTAL (NBUF * STG)   // 98304

// ---- device scratch ----
__device__ __half g_Kh  [(size_t)BATCH*SHW*CKD];   // [b][kv][c] fp16
__device__ __half g_Vh  [(size_t)BATCH*CKD*SHW];   // [b][c][kv] fp16
__device__ __half g_Qt_hi[(size_t)BATCH*HW*CKD];   // [b][q][c] fp16 (x log2e)
__device__ __half g_Qt_lo[(size_t)BATCH*HW*CKD];   // fp16 residual
__device__ float g_Opart[4][(size_t)BATCH*HW*CKD];
__device__ float g_Lpart[4][(size_t)BATCH*HW];
__device__ float g_Mpart[4][(size_t)BATCH*HW];
__device__ float g_maskV[BATCH][CKD];

// ---- helpers ----
__device__ __forceinline__ uint32_t smem_u32(const void* p) {
    uint32_t a;
    asm("{ .reg .u64 t; cvta.to.shared.u64 t, %1; cvt.u32.u64 %0, t; }" : "=r"(a) : "l"(p));
    return a;
}
__device__ __forceinline__ uint32_t cvt2_f16(float lo, float hi) {
    uint32_t r;
    asm("cvt.rn.f16x2.f32 %0, %1, %2;" : "=r"(r) : "f"(hi), "f"(lo));
    return r;
}
__device__ __forceinline__ uint32_t ex2_f16x2(uint32_t x) {
    uint32_t r;
    asm("ex2.approx.f16x2 %0, %1;" : "=r"(r) : "r"(x));
    return r;
}
__device__ __forceinline__ void unpack_f16(uint32_t h, float& x, float& y) {
    asm("{.reg .f16 a,b; mov.b32 {a,b}, %2; cvt.f32.f16 %0, a; cvt.f32.f16 %1, b;}"
        : "=f"(x), "=f"(y) : "r"(h));
}
__device__ __forceinline__ float ex2f(float x) {
    float r; asm("ex2.approx.ftz.f32 %0, %1;" : "=f"(r) : "f"(x)); return r;
}
__device__ __forceinline__ void split2h(float x0, float x1, uint32_t& h, uint32_t& l) {
    h = cvt2_f16(x0, x1);
    float a0, a1;
    unpack_f16(h, a0, a1);
    l = cvt2_f16(x0 - a0, x1 - a1);
}

#define LDSM4(r, a) \
    asm volatile("ldmatrix.sync.aligned.m8n8.x4.shared.b16 {%0,%1,%2,%3}, [%4];" \
        : "=r"((r)[0]), "=r"((r)[1]), "=r"((r)[2]), "=r"((r)[3]) : "r"(a))

#define MMAH(c, a, b0, b1) \
    asm volatile("mma.sync.aligned.m16n8k16.row.col.f32.f16.f16.f32 " \
        "{%0,%1,%2,%3}, {%4,%5,%6,%7}, {%8,%9}, {%0,%1,%2,%3};" \
        : "+f"((c)[0]), "+f"((c)[1]), "+f"((c)[2]), "+f"((c)[3]) \
        : "r"((a)[0]), "r"((a)[1]), "r"((a)[2]), "r"((a)[3]), "r"(b0), "r"(b1))

#define CPA16(dst, src) \
    asm volatile("cp.async.cg.shared.global [%0], [%1], 16;" :: "r"(dst), "l"(src))

// ---- prepass: merged K/Q transpose (fp16) ----
__global__ void kqtrans_kernel(const float* __restrict__ mk,
                               const float* __restrict__ qq) {
    __shared__ float st[128][65];
    int blk = blockIdx.x;
    int tid = threadIdx.x;
    if (blk == 0 && tid < BATCH * CKD) ((float*)g_maskV)[tid] = 0.f;

    const float* src;
    size_t ob;
    float scale;
    bool isq = (blk >= 512);
    if (!isq) {
        int hwt = blk & 31, b = (blk >> 5) & 1, s = blk >> 6;
        int hw0 = hwt * 128;
        src = mk + (((size_t)s * BATCH + b) * CKD) * HW + hw0;
        ob = ((size_t)b * SHW + (size_t)s * HW + hw0) * CKD;
        scale = 1.0f;
    } else {
        int q = blk - 512;
        int hwt = q & 31, b = q >> 5;
        int hw0 = hwt * 128;
        src = qq + ((size_t)b * CKD) * HW + hw0;
        ob = ((size_t)b * HW + hw0) * CKD;
        scale = LOG2E;
    }
    for (int i = tid; i < 2048; i += TPB) {
        int c = i >> 5, j4 = (i & 31) * 4;
        float4 v = *(const float4*)(src + (size_t)c * HW + j4);
        st[j4][c] = v.x * scale; st[j4+1][c] = v.y * scale;
        st[j4+2][c] = v.z * scale; st[j4+3][c] = v.w * scale;
    }
    __syncthreads();
    for (int i = tid; i < 1024; i += TPB) {
        int r = i >> 3, c0 = (i & 7) * 8;
        uint32_t h4[4], l4[4];
        #pragma unroll
        for (int k = 0; k < 4; k++) split2h(st[r][c0+2*k], st[r][c0+2*k+1], h4[k], l4[k]);
        if (!isq) {
            *(uint4*)(g_Kh + ob + (size_t)r * CKD + c0) = *(uint4*)h4;
        } else {
            *(uint4*)(g_Qt_hi + ob + (size_t)r * CKD + c0) = *(uint4*)h4;
            *(uint4*)(g_Qt_lo + ob + (size_t)r * CKD + c0) = *(uint4*)l4;
        }
    }
}

// V convert fp16 + fused maskV reduction
__global__ void vconv_kernel(const float* __restrict__ mv,
                             const float* __restrict__ disp,
                             const int* __restrict__ seq) {
    __shared__ float red[8];
    int tid = threadIdx.x;
    size_t i = (size_t)blockIdx.x * TPB + tid;
    size_t e4 = i * 4;
    int hw = (int)(e4 & 4095);
    size_t t = e4 >> 12;
    int c = (int)(t & 63); t >>= 6;
    int b = (int)(t & 1);  int s = (int)(t >> 1);
    float4 v = *(const float4*)(mv + e4);
    size_t o = (((size_t)b * CKD + c) * SHW) + (size_t)s * HW + hw;
    uint2 hh;
    hh.x = cvt2_f16(v.x, v.y);
    hh.y = cvt2_f16(v.z, v.w);
    *(uint2*)(g_Vh + o) = hh;

    float d0 = (float)seq[(b * S_FR + s) * 2 + 0] - 5.0f;
    float d1 = (float)seq[(b * S_FR + s) * 2 + 1] - 5.0f;
    float dist = sqrtf(d1 * d1 + d0 * d0);
    const float* dp = disp + (size_t)b * HW + hw;
    float a = 0.f;
    if (fabsf(dist * dp[0]) > RADIUS) a += v.x;
    if (fabsf(dist * dp[1]) > RADIUS) a += v.y;
    if (fabsf(dist * dp[2]) > RADIUS) a += v.z;
    if (fabsf(dist * dp[3]) > RADIUS) a += v.w;
    #pragma unroll
    for (int off = 16; off; off >>= 1) a += __shfl_xor_sync(0xffffffffu, a, off);
    if ((tid & 31) == 0) red[tid >> 5] = a;
    __syncthreads();
    if (tid == 0) {
        float tot = 0.f;
        #pragma unroll
        for (int w = 0; w < 8; w++) tot += red[w];
        atomicAdd(&g_maskV[b][c], tot * WEIGHTC);
    }
}

// ---- main attention kernel: 16 warps = 8 M-groups (m16) x 2 key-slices ----
// Per 2-tile pair: QK(tt) | softmax | [PV(tt) || QK(tt+1)] | softmax | PV(tt+1).
// Single score buffer (c reused after softmax), R13 register footprint.
__global__ __launch_bounds__(ATPB, 1) void attn_mma_kernel() {
    extern __shared__ char smem[];
    uint32_t sb = smem_u32(smem);
    int tid = threadIdx.x, wid = tid >> 5, L = tid & 31;
    int blk = blockIdx.x;                 // 128
    int h  = blk & 1;
    int qt = (blk >> 1) & 31;
    int b  = blk >> 6;
    int q0 = qt * 128;
    int kv0 = h * 16384;
    int mw = wid & 7;      // M group (16 rows)
    int nw = wid >> 3;     // key half

    // ---- Q fragments straight from gmem (A-frag layout, m16, fp16 hi/lo) ----
    uint32_t qh[4][4], ql[4][4];
    {
        const __half* QbH = g_Qt_hi + ((size_t)b * HW + q0) * CKD;
        const __half* QbL = g_Qt_lo + ((size_t)b * HW + q0) * CKD;
        int r = mw * 16 + (L >> 2);
        #pragma unroll
        for (int k = 0; k < 4; k++) {
            int cc = 2 * (L & 3) + 16 * k;
            qh[k][0] = *(const uint32_t*)(QbH + (size_t)r * CKD + cc);
            qh[k][1] = *(const uint32_t*)(QbH + (size_t)(r + 8) * CKD + cc);
            qh[k][2] = *(const uint32_t*)(QbH + (size_t)r * CKD + cc + 8);
            qh[k][3] = *(const uint32_t*)(QbH + (size_t)(r + 8) * CKD + cc + 8);
            ql[k][0] = *(const uint32_t*)(QbL + (size_t)r * CKD + cc);
            ql[k][1] = *(const uint32_t*)(QbL + (size_t)(r + 8) * CKD + cc);
            ql[k][2] = *(const uint32_t*)(QbL + (size_t)r * CKD + cc + 8);
            ql[k][3] = *(const uint32_t*)(QbL + (size_t)(r + 8) * CKD + cc + 8);
        }
    }

    const __half* KH = g_Kh + ((size_t)b * SHW + kv0) * CKD;
    const __half* VH = g_Vh + (size_t)b * CKD * SHW + kv0;

    int r0 = tid >> 3, c0 = tid & 7;
    uint32_t so0 = (uint32_t)(r0 * 128 + ((c0 ^ (r0 & 7)) * 16));

    int lrow = (L & 7) + ((L & 16) >> 1);
    int lcb  = (L >> 3) & 1;
    uint32_t lro = (uint32_t)lrow * 128;
    int lsw = lrow & 7;

#define LOAD_TILE(tt, bufidx) do { \
    uint32_t bb = sb + (uint32_t)(bufidx) * STG; \
    size_t kvo = (size_t)(tt) * 64; \
    CPA16(bb + so0,        KH + (kvo + r0) * CKD + c0 * 8); \
    CPA16(bb + 8192 + so0, VH + (size_t)r0 * SHW + kvo + c0 * 8); \
    asm volatile("cp.async.commit_group;"); \
} while (0)

    LOAD_TILE(0, 0);
    LOAD_TILE(1, 1);
    LOAD_TILE(2, 2);
    LOAD_TILE(3, 3);

    float o[8][4];
    #pragma unroll
    for (int i = 0; i < 8; i++) o[i][0] = o[i][1] = o[i][2] = o[i][3] = 0.f;
    float lacc[2] = {0.f, 0.f};
    float mrow[2] = {-1e30f, -1e30f};
    float c[4][4];
    uint32_t ph[8];

// QK(t) -> c (plain), same MMA order as R13
#define QK_TILE(t) do { \
    uint32_t kb = sb + (uint32_t)((t) % NBUF) * STG; \
    _Pragma("unroll") \
    for (int i = 0; i < 4; i++) c[i][0] = c[i][1] = c[i][2] = c[i][3] = 0.f; \
    _Pragma("unroll") \
    for (int k = 0; k < 4; k++) { \
        uint32_t coff = (uint32_t)(((2 * k + lcb) ^ lsw) * 16); \
        uint32_t base0 = kb + (uint32_t)(nw * 2 + 0) * 2048 + lro; \
        uint32_t base1 = kb + (uint32_t)(nw * 2 + 1) * 2048 + lro; \
        uint32_t bh0[4], bh1[4]; \
        LDSM4(bh0, base0 + coff); \
        LDSM4(bh1, base1 + coff); \
        MMAH(c[0], qh[k], bh0[0], bh0[1]); \
        MMAH(c[2], qh[k], bh1[0], bh1[1]); \
        MMAH(c[1], qh[k], bh0[2], bh0[3]); \
        MMAH(c[3], qh[k], bh1[2], bh1[3]); \
        MMAH(c[0], ql[k], bh0[0], bh0[1]); \
        MMAH(c[2], ql[k], bh1[0], bh1[1]); \
        MMAH(c[1], ql[k], bh0[2], bh0[3]); \
        MMAH(c[3], ql[k], bh1[2], bh1[3]); \
    } \
} while (0)

// softmax of c -> ph, update o/l/m (identical arithmetic to R13)
#define SOFTMAX_TILE() do { \
    { \
        float a0 = fmaxf(fmaxf(c[0][0], c[0][1]), fmaxf(c[1][0], c[1][1])); \
        a0 = fmaxf(a0, fmaxf(fmaxf(c[2][0], c[2][1]), fmaxf(c[3][0], c[3][1]))); \
        float a1 = fmaxf(fmaxf(c[0][2], c[0][3]), fmaxf(c[1][2], c[1][3])); \
        a1 = fmaxf(a1, fmaxf(fmaxf(c[2][2], c[2][3]), fmaxf(c[3][2], c[3][3]))); \
        a0 = fmaxf(a0, __shfl_xor_sync(0xffffffffu, a0, 1)); \
        a0 = fmaxf(a0, __shfl_xor_sync(0xffffffffu, a0, 2)); \
        a1 = fmaxf(a1, __shfl_xor_sync(0xffffffffu, a1, 1)); \
        a1 = fmaxf(a1, __shfl_xor_sync(0xffffffffu, a1, 2)); \
        if (a0 > mrow[0]) { \
            float sc = ex2f(mrow[0] - a0); \
            lacc[0] *= sc; \
            _Pragma("unroll") \
            for (int vt = 0; vt < 8; vt++) { o[vt][0] *= sc; o[vt][1] *= sc; } \
            mrow[0] = a0; \
        } \
        if (a1 > mrow[1]) { \
            float sc = ex2f(mrow[1] - a1); \
            lacc[1] *= sc; \
            _Pragma("unroll") \
            for (int vt = 0; vt < 8; vt++) { o[vt][2] *= sc; o[vt][3] *= sc; } \
            mrow[1] = a1; \
        } \
    } \
    _Pragma("unroll") \
    for (int jt = 0; jt < 4; jt++) { \
        int base = (jt >> 1) * 4 + (jt & 1) * 2; \
        uint32_t d0 = cvt2_f16(c[jt][0] - mrow[0], c[jt][1] - mrow[0]); \
        uint32_t d1 = cvt2_f16(c[jt][2] - mrow[1], c[jt][3] - mrow[1]); \
        uint32_t p0 = ex2_f16x2(d0); \
        uint32_t p1 = ex2_f16x2(d1); \
        ph[base]     = p0; \
        ph[base + 1] = p1; \
        float f0, f1, f2, f3; \
        unpack_f16(p0, f0, f1); \
        unpack_f16(p1, f2, f3); \
        lacc[0] += f0 + f1; \
        lacc[1] += f2 + f3; \
    } \
} while (0)

// PV(t) plain (R13 order)
#define PV_TILE(t) do { \
    uint32_t kb = sb + (uint32_t)((t) % NBUF) * STG; \
    _Pragma("unroll") \
    for (int jl = 0; jl < 2; jl++) { \
        int jg = nw * 2 + jl; \
        uint32_t* Ah = ph + jl * 4; \
        uint32_t coff = (uint32_t)(((2 * jg + lcb) ^ lsw) * 16); \
        _Pragma("unroll") \
        for (int np = 0; np < 2; np++) { \
            uint32_t va[4], vb[4]; \
            LDSM4(va, kb + 8192 + (uint32_t)(2 * np) * 2048 + lro + coff); \
            LDSM4(vb, kb + 8192 + (uint32_t)(2 * np + 1) * 2048 + lro + coff); \
            MMAH(o[4*np],     Ah, va[0], va[1]); \
            MMAH(o[4*np + 2], Ah, vb[0], vb[1]); \
            MMAH(o[4*np + 1], Ah, va[2], va[3]); \
            MMAH(o[4*np + 3], Ah, vb[2], vb[3]); \
        } \
    } \
} while (0)

// PV(t) interleaved with QK(t+1)->c (c dead before entry; reused)
#define PVQK_TILE(t) do { \
    uint32_t kbV = sb + (uint32_t)((t) % NBUF) * STG; \
    uint32_t kbK = sb + (uint32_t)(((t) + 1) % NBUF) * STG; \
    _Pragma("unroll") \
    for (int i = 0; i < 4; i++) c[i][0] = c[i][1] = c[i][2] = c[i][3] = 0.f; \
    _Pragma("unroll") \
    for (int kk = 0; kk < 4; kk++) { \
        int jl = kk >> 1, np = kk & 1; \
        int jg = nw * 2 + jl; \
        uint32_t coffV = (uint32_t)(((2 * jg + lcb) ^ lsw) * 16); \
        uint32_t coffK = (uint32_t)(((2 * kk + lcb) ^ lsw) * 16); \
        uint32_t va[4], vb[4], bh0[4], bh1[4]; \
        LDSM4(va, kbV + 8192 + (uint32_t)(2 * np) * 2048 + lro + coffV); \
        LDSM4(vb, kbV + 8192 + (uint32_t)(2 * np + 1) * 2048 + lro + coffV); \
        LDSM4(bh0, kbK + (uint32_t)(nw * 2 + 0) * 2048 + lro + coffK); \
        LDSM4(bh1, kbK + (uint32_t)(nw * 2 + 1) * 2048 + lro + coffK); \
        uint32_t* Ah = ph + jl * 4; \
        MMAH(c[0], qh[kk], bh0[0], bh0[1]); \
        MMAH(o[4*np],     Ah, va[0], va[1]); \
        MMAH(c[2], qh[kk], bh1[0], bh1[1]); \
        MMAH(o[4*np + 2], Ah, vb[0], vb[1]); \
        MMAH(c[1], qh[kk], bh0[2], bh0[3]); \
        MMAH(o[4*np + 1], Ah, va[2], va[3]); \
        MMAH(c[3], qh[kk], bh1[2], bh1[3]); \
        MMAH(o[4*np + 3], Ah, vb[2], vb[3]); \
        MMAH(c[0], ql[kk], bh0[0], bh0[1]); \
        MMAH(c[2], ql[kk], bh1[0], bh1[1]); \
        MMAH(c[1], ql[kk], bh0[2], bh0[3]); \
        MMAH(c[3], ql[kk], bh1[2], bh1[3]); \
    } \
} while (0)

    for (int tt = 0; tt < NT; tt += 2) {
        if (tt >= NT - 2) { asm volatile("cp.async.wait_group 0;"); }
        else              { asm volatile("cp.async.wait_group 2;"); }
        __syncthreads();   // publish tiles tt,tt+1; all warps done with <= tt-1
        if (tt + 4 < NT) LOAD_TILE(tt + 4, (tt + 4) % NBUF);
        if (tt + 5 < NT) LOAD_TILE(tt + 5, (tt + 5) % NBUF);

        QK_TILE(tt);
        SOFTMAX_TILE();
        PVQK_TILE(tt);        // PV(tt) || QK(tt+1) -> c
        SOFTMAX_TILE();
        PV_TILE(tt + 1);
    }

    // ---- epilogue: store partials (slot = h*2 + nw) ----
    int slot = h * 2 + nw;
    {
        float l0 = lacc[0], l1 = lacc[1];
        l0 += __shfl_xor_sync(0xffffffffu, l0, 1);
        l0 += __shfl_xor_sync(0xffffffffu, l0, 2);
        l1 += __shfl_xor_sync(0xffffffffu, l1, 1);
        l1 += __shfl_xor_sync(0xffffffffu, l1, 2);
        int mg = q0 + mw * 16 + (L >> 2);
        float* op = g_Opart[slot] + ((size_t)b * HW + mg) * CKD;
        #pragma unroll
        for (int vt = 0; vt < 8; vt++) {
            int v = vt * 8 + (L & 3) * 2;
            *(float2*)(op + v)           = make_float2(o[vt][0], o[vt][1]);
            *(float2*)(op + 8 * CKD + v) = make_float2(o[vt][2], o[vt][3]);
        }
        if ((L & 3) == 0) {
            g_Lpart[slot][(size_t)b * HW + mg]     = l0;
            g_Lpart[slot][(size_t)b * HW + mg + 8] = l1;
            g_Mpart[slot][(size_t)b * HW + mg]     = mrow[0];
            g_Mpart[slot][(size_t)b * HW + mg + 8] = mrow[1];
        }
    }
}

// ---- combine: FA split-k merge, 512 blocks x 16 rows ----
__global__ void combine_kernel(float* __restrict__ out) {
    __shared__ float st[16][65];
    int g0 = blockIdx.x * 16;
    int tid = threadIdx.x;
    int b = g0 >> 12;
    {
        int r = tid >> 4, v4 = (tid & 15) * 4;
        int row = g0 + r;
        float m0 = g_Mpart[0][row], m1 = g_Mpart[1][row];
        float m2 = g_Mpart[2][row], m3 = g_Mpart[3][row];
        float ms = fmaxf(fmaxf(m0, m1), fmaxf(m2, m3));
        float w0 = ex2f(m0 - ms), w1 = ex2f(m1 - ms);
        float w2 = ex2f(m2 - ms), w3 = ex2f(m3 - ms);
        float lsum = w0 * g_Lpart[0][row] + w1 * g_Lpart[1][row]
                   + w2 * g_Lpart[2][row] + w3 * g_Lpart[3][row];
        float inv = 1.0f / lsum;
        size_t idx = (size_t)row * CKD + v4;
        float4 a0 = *(const float4*)(g_Opart[0] + idx);
        float4 a1 = *(const float4*)(g_Opart[1] + idx);
        float4 a2 = *(const float4*)(g_Opart[2] + idx);
        float4 a3 = *(const float4*)(g_Opart[3] + idx);
        st[r][v4]   = (w0*a0.x + w1*a1.x + w2*a2.x + w3*a3.x) * inv;
        st[r][v4+1] = (w0*a0.y + w1*a1.y + w2*a2.y + w3*a3.y) * inv;
        st[r][v4+2] = (w0*a0.z + w1*a1.z + w2*a2.z + w3*a3.z) * inv;
        st[r][v4+3] = (w0*a0.w + w1*a1.w + w2*a2.w + w3*a3.w) * inv;
    }
    __syncthreads();
    float* ob = out + (size_t)b * CKD * HW;
    int qb = g0 & 4095;
    {
        int v = tid >> 2, r4 = (tid & 3) * 4;
        float mval = g_maskV[b][v];
        float4 w;
        w.x = st[r4][v]   + mval;
        w.y = st[r4+1][v] + mval;
        w.z = st[r4+2][v] + mval;
        w.w = st[r4+3][v] + mval;
        *(float4*)(ob + (size_t)v * HW + qb + r4) = w;
    }
}

// ---- launch ----
extern "C" void kernel_launch(void* const* d_in, const int* in_sizes, int n_in,
                              void* d_out, int out_size) {
    const float* mk   = (const float*)d_in[0];
    const float* mv   = (const float*)d_in[1];
    const float* qq   = (const float*)d_in[2];
    const float* disp = (const float*)d_in[3];
    const int*   seq  = (const int*)d_in[4];
    float* out = (float*)d_out;

    kqtrans_kernel<<<576, TPB>>>(mk, qq);
    vconv_kernel<<<4096, TPB>>>(mv, disp, seq);

    cudaFuncSetAttribute(attn_mma_kernel, cudaFuncAttributeMaxDynamicSharedMemorySize, SMEM_TOTAL);
    attn_mma_kernel<<<128, ATPB, SMEM_TOTAL>>>();

    combine_kernel<<<512, TPB>>>(out);
}

// round 16
// speedup vs baseline: 1.0472x; 1.0001x over previous
#include <cuda_runtime.h>
#include <cuda_bf16.h>
#include <cuda_fp16.h>
#include <math.h>
#include <stdint.h>

#define S_FR   8
#define BATCH  2
#define CKD    64
#define HW     4096
#define SHW    32768
#define RADIUS 0.1f
#define WEIGHTC (0.2f / (8.0f * 64.0f * 64.0f))
#define LOG2E   1.4426950408889634f
#define TPB    256          // prepass blocks
#define ATPB   512          // attention kernel: 16 warps
#define NT     256          // KV tiles per CTA (16384 keys / 64)
#define STG    16384        // stage: KH 8K | VH 8K
#define NBUF   6
#define SMEM_TOTAL (NBUF * STG)   // 98304

// ---- device scratch ----
__device__ __half g_Kh  [(size_t)BATCH*SHW*CKD];   // [b][kv][c] fp16
__device__ __half g_Vh  [(size_t)BATCH*CKD*SHW];   // [b][c][kv] fp16
__device__ __half g_Qt_hi[(size_t)BATCH*HW*CKD];   // [b][q][c] fp16 (x log2e)
__device__ __half g_Qt_lo[(size_t)BATCH*HW*CKD];   // fp16 residual
__device__ float g_Opart[4][(size_t)BATCH*HW*CKD];
__device__ float g_Lpart[4][(size_t)BATCH*HW];
__device__ float g_Mpart[4][(size_t)BATCH*HW];
__device__ float g_maskV[BATCH][CKD];

// ---- helpers ----
__device__ __forceinline__ uint32_t smem_u32(const void* p) {
    uint32_t a;
    asm("{ .reg .u64 t; cvta.to.shared.u64 t, %1; cvt.u32.u64 %0, t; }" : "=r"(a) : "l"(p));
    return a;
}
__device__ __forceinline__ uint32_t cvt2_f16(float lo, float hi) {
    uint32_t r;
    asm("cvt.rn.f16x2.f32 %0, %1, %2;" : "=r"(r) : "f"(hi), "f"(lo));
    return r;
}
__device__ __forceinline__ uint32_t ex2_f16x2(uint32_t x) {
    uint32_t r;
    asm("ex2.approx.f16x2 %0, %1;" : "=r"(r) : "r"(x));
    return r;
}
__device__ __forceinline__ void unpack_f16(uint32_t h, float& x, float& y) {
    asm("{.reg .f16 a,b; mov.b32 {a,b}, %2; cvt.f32.f16 %0, a; cvt.f32.f16 %1, b;}"
        : "=f"(x), "=f"(y) : "r"(h));
}
__device__ __forceinline__ float ex2f(float x) {
    float r; asm("ex2.approx.ftz.f32 %0, %1;" : "=f"(r) : "f"(x)); return r;
}
__device__ __forceinline__ void split2h(float x0, float x1, uint32_t& h, uint32_t& l) {
    h = cvt2_f16(x0, x1);
    float a0, a1;
    unpack_f16(h, a0, a1);
    l = cvt2_f16(x0 - a0, x1 - a1);
}

#define LDSM4(r, a) \
    asm volatile("ldmatrix.sync.aligned.m8n8.x4.shared.b16 {%0,%1,%2,%3}, [%4];" \
        : "=r"((r)[0]), "=r"((r)[1]), "=r"((r)[2]), "=r"((r)[3]) : "r"(a))

#define MMAH(c, a, b0, b1) \
    asm volatile("mma.sync.aligned.m16n8k16.row.col.f32.f16.f16.f32 " \
        "{%0,%1,%2,%3}, {%4,%5,%6,%7}, {%8,%9}, {%0,%1,%2,%3};" \
        : "+f"((c)[0]), "+f"((c)[1]), "+f"((c)[2]), "+f"((c)[3]) \
        : "r"((a)[0]), "r"((a)[1]), "r"((a)[2]), "r"((a)[3]), "r"(b0), "r"(b1))

#define CPA16(dst, src) \
    asm volatile("cp.async.cg.shared.global [%0], [%1], 16;" :: "r"(dst), "l"(src))

// ---- prepass: merged K/Q transpose (fp16) ----
__global__ void kqtrans_kernel(const float* __restrict__ mk,
                               const float* __restrict__ qq) {
    __shared__ float st[128][65];
    int blk = blockIdx.x;
    int tid = threadIdx.x;
    if (blk == 0 && tid < BATCH * CKD) ((float*)g_maskV)[tid] = 0.f;

    const float* src;
    size_t ob;
    float scale;
    bool isq = (blk >= 512);
    if (!isq) {
        int hwt = blk & 31, b = (blk >> 5) & 1, s = blk >> 6;
        int hw0 = hwt * 128;
        src = mk + (((size_t)s * BATCH + b) * CKD) * HW + hw0;
        ob = ((size_t)b * SHW + (size_t)s * HW + hw0) * CKD;
        scale = 1.0f;
    } else {
        int q = blk - 512;
        int hwt = q & 31, b = q >> 5;
        int hw0 = hwt * 128;
        src = qq + ((size_t)b * CKD) * HW + hw0;
        ob = ((size_t)b * HW + hw0) * CKD;
        scale = LOG2E;
    }
    for (int i = tid; i < 2048; i += TPB) {
        int c = i >> 5, j4 = (i & 31) * 4;
        float4 v = *(const float4*)(src + (size_t)c * HW + j4);
        st[j4][c] = v.x * scale; st[j4+1][c] = v.y * scale;
        st[j4+2][c] = v.z * scale; st[j4+3][c] = v.w * scale;
    }
    __syncthreads();
    for (int i = tid; i < 1024; i += TPB) {
        int r = i >> 3, c0 = (i & 7) * 8;
        uint32_t h4[4], l4[4];
        #pragma unroll
        for (int k = 0; k < 4; k++) split2h(st[r][c0+2*k], st[r][c0+2*k+1], h4[k], l4[k]);
        if (!isq) {
            *(uint4*)(g_Kh + ob + (size_t)r * CKD + c0) = *(uint4*)h4;
        } else {
            *(uint4*)(g_Qt_hi + ob + (size_t)r * CKD + c0) = *(uint4*)h4;
            *(uint4*)(g_Qt_lo + ob + (size_t)r * CKD + c0) = *(uint4*)l4;
        }
    }
}

// V convert fp16 + fused maskV reduction
__global__ void vconv_kernel(const float* __restrict__ mv,
                             const float* __restrict__ disp,
                             const int* __restrict__ seq) {
    __shared__ float red[8];
    int tid = threadIdx.x;
    size_t i = (size_t)blockIdx.x * TPB + tid;
    size_t e4 = i * 4;
    int hw = (int)(e4 & 4095);
    size_t t = e4 >> 12;
    int c = (int)(t & 63); t >>= 6;
    int b = (int)(t & 1);  int s = (int)(t >> 1);
    float4 v = *(const float4*)(mv + e4);
    size_t o = (((size_t)b * CKD + c) * SHW) + (size_t)s * HW + hw;
    uint2 hh;
    hh.x = cvt2_f16(v.x, v.y);
    hh.y = cvt2_f16(v.z, v.w);
    *(uint2*)(g_Vh + o) = hh;

    float d0 = (float)seq[(b * S_FR + s) * 2 + 0] - 5.0f;
    float d1 = (float)seq[(b * S_FR + s) * 2 + 1] - 5.0f;
    float dist = sqrtf(d1 * d1 + d0 * d0);
    const float* dp = disp + (size_t)b * HW + hw;
    float a = 0.f;
    if (fabsf(dist * dp[0]) > RADIUS) a += v.x;
    if (fabsf(dist * dp[1]) > RADIUS) a += v.y;
    if (fabsf(dist * dp[2]) > RADIUS) a += v.z;
    if (fabsf(dist * dp[3]) > RADIUS) a += v.w;
    #pragma unroll
    for (int off = 16; off; off >>= 1) a += __shfl_xor_sync(0xffffffffu, a, off);
    if ((tid & 31) == 0) red[tid >> 5] = a;
    __syncthreads();
    if (tid == 0) {
        float tot = 0.f;
        #pragma unroll
        for (int w = 0; w < 8; w++) tot += red[w];
        atomicAdd(&g_maskV[b][c], tot * WEIGHTC);
    }
}

// ---- main attention kernel: 16 warps = 8 M-groups (m16) x 2 key-slices ----
// Per 2-tile pair: QK(tt) | softmax | [PV(tt) || QK(tt+1)] | softmax | PV(tt+1).
// Single score buffer (c reused after softmax), R13 register footprint.
__global__ __launch_bounds__(ATPB, 1) void attn_mma_kernel() {
    extern __shared__ char smem[];
    uint32_t sb = smem_u32(smem);
    int tid = threadIdx.x, wid = tid >> 5, L = tid & 31;
    int blk = blockIdx.x;                 // 128
    int h  = blk & 1;
    int qt = (blk >> 1) & 31;
    int b  = blk >> 6;
    int q0 = qt * 128;
    int kv0 = h * 16384;
    int mw = wid & 7;      // M group (16 rows)
    int nw = wid >> 3;     // key half

    // ---- Q fragments straight from gmem (A-frag layout, m16, fp16 hi/lo) ----
    uint32_t qh[4][4], ql[4][4];
    {
        const __half* QbH = g_Qt_hi + ((size_t)b * HW + q0) * CKD;
        const __half* QbL = g_Qt_lo + ((size_t)b * HW + q0) * CKD;
        int r = mw * 16 + (L >> 2);
        #pragma unroll
        for (int k = 0; k < 4; k++) {
            int cc = 2 * (L & 3) + 16 * k;
            qh[k][0] = *(const uint32_t*)(QbH + (size_t)r * CKD + cc);
            qh[k][1] = *(const uint32_t*)(QbH + (size_t)(r + 8) * CKD + cc);
            qh[k][2] = *(const uint32_t*)(QbH + (size_t)r * CKD + cc + 8);
            qh[k][3] = *(const uint32_t*)(QbH + (size_t)(r + 8) * CKD + cc + 8);
            ql[k][0] = *(const uint32_t*)(QbL + (size_t)r * CKD + cc);
            ql[k][1] = *(const uint32_t*)(QbL + (size_t)(r + 8) * CKD + cc);
            ql[k][2] = *(const uint32_t*)(QbL + (size_t)r * CKD + cc + 8);
            ql[k][3] = *(const uint32_t*)(QbL + (size_t)(r + 8) * CKD + cc + 8);
        }
    }

    const __half* KH = g_Kh + ((size_t)b * SHW + kv0) * CKD;
    const __half* VH = g_Vh + (size_t)b * CKD * SHW + kv0;

    int r0 = tid >> 3, c0 = tid & 7;
    uint32_t so0 = (uint32_t)(r0 * 128 + ((c0 ^ (r0 & 7)) * 16));

    int lrow = (L & 7) + ((L & 16) >> 1);
    int lcb  = (L >> 3) & 1;
    uint32_t lro = (uint32_t)lrow * 128;
    int lsw = lrow & 7;

#define LOAD_TILE(tt, bufidx) do { \
    uint32_t bb = sb + (uint32_t)(bufidx) * STG; \
    size_t kvo = (size_t)(tt) * 64; \
    CPA16(bb + so0,        KH + (kvo + r0) * CKD + c0 * 8); \
    CPA16(bb + 8192 + so0, VH + (size_t)r0 * SHW + kvo + c0 * 8); \
    asm volatile("cp.async.commit_group;"); \
} while (0)

    LOAD_TILE(0, 0);
    LOAD_TILE(1, 1);
    LOAD_TILE(2, 2);
    LOAD_TILE(3, 3);

    float o[8][4];
    #pragma unroll
    for (int i = 0; i < 8; i++) o[i][0] = o[i][1] = o[i][2] = o[i][3] = 0.f;
    float lacc[2] = {0.f, 0.f};
    float mrow[2] = {-1e30f, -1e30f};
    float c[4][4];
    uint32_t ph[8];

// QK(t) -> c (plain), same MMA order as R13
#define QK_TILE(t) do { \
    uint32_t kb = sb + (uint32_t)((t) % NBUF) * STG; \
    _Pragma("unroll") \
    for (int i = 0; i < 4; i++) c[i][0] = c[i][1] = c[i][2] = c[i][3] = 0.f; \
    _Pragma("unroll") \
    for (int k = 0; k < 4; k++) { \
        uint32_t coff = (uint32_t)(((2 * k + lcb) ^ lsw) * 16); \
        uint32_t base0 = kb + (uint32_t)(nw * 2 + 0) * 2048 + lro; \
        uint32_t base1 = kb + (uint32_t)(nw * 2 + 1) * 2048 + lro; \
        uint32_t bh0[4], bh1[4]; \
        LDSM4(bh0, base0 + coff); \
        LDSM4(bh1, base1 + coff); \
        MMAH(c[0], qh[k], bh0[0], bh0[1]); \
        MMAH(c[2], qh[k], bh1[0], bh1[1]); \
        MMAH(c[1], qh[k], bh0[2], bh0[3]); \
        MMAH(c[3], qh[k], bh1[2], bh1[3]); \
        MMAH(c[0], ql[k], bh0[0], bh0[1]); \
        MMAH(c[2], ql[k], bh1[0], bh1[1]); \
        MMAH(c[1], ql[k], bh0[2], bh0[3]); \
        MMAH(c[3], ql[k], bh1[2], bh1[3]); \
    } \
} while (0)

// softmax of c -> ph, update o/l/m (identical arithmetic to R13)
#define SOFTMAX_TILE() do { \
    { \
        float a0 = fmaxf(fmaxf(c[0][0], c[0][1]), fmaxf(c[1][0], c[1][1])); \
        a0 = fmaxf(a0, fmaxf(fmaxf(c[2][0], c[2][1]), fmaxf(c[3][0], c[3][1]))); \
        float a1 = fmaxf(fmaxf(c[0][2], c[0][3]), fmaxf(c[1][2], c[1][3])); \
        a1 = fmaxf(a1, fmaxf(fmaxf(c[2][2], c[2][3]), fmaxf(c[3][2], c[3][3]))); \
        a0 = fmaxf(a0, __shfl_xor_sync(0xffffffffu, a0, 1)); \
        a0 = fmaxf(a0, __shfl_xor_sync(0xffffffffu, a0, 2)); \
        a1 = fmaxf(a1, __shfl_xor_sync(0xffffffffu, a1, 1)); \
        a1 = fmaxf(a1, __shfl_xor_sync(0xffffffffu, a1, 2)); \
        if (a0 > mrow[0]) { \
            float sc = ex2f(mrow[0] - a0); \
            lacc[0] *= sc; \
            _Pragma("unroll") \
            for (int vt = 0; vt < 8; vt++) { o[vt][0] *= sc; o[vt][1] *= sc; } \
            mrow[0] = a0; \
        } \
        if (a1 > mrow[1]) { \
            float sc = ex2f(mrow[1] - a1); \
            lacc[1] *= sc; \
            _Pragma("unroll") \
            for (int vt = 0; vt < 8; vt++) { o[vt][2] *= sc; o[vt][3] *= sc; } \
            mrow[1] = a1; \
        } \
    } \
    _Pragma("unroll") \
    for (int jt = 0; jt < 4; jt++) { \
        int base = (jt >> 1) * 4 + (jt & 1) * 2; \
        uint32_t d0 = cvt2_f16(c[jt][0] - mrow[0], c[jt][1] - mrow[0]); \
        uint32_t d1 = cvt2_f16(c[jt][2] - mrow[1], c[jt][3] - mrow[1]); \
        uint32_t p0 = ex2_f16x2(d0); \
        uint32_t p1 = ex2_f16x2(d1); \
        ph[base]     = p0; \
        ph[base + 1] = p1; \
        float f0, f1, f2, f3; \
        unpack_f16(p0, f0, f1); \
        unpack_f16(p1, f2, f3); \
        lacc[0] += f0 + f1; \
        lacc[1] += f2 + f3; \
    } \
} while (0)

// PV(t) plain (R13 order)
#define PV_TILE(t) do { \
    uint32_t kb = sb + (uint32_t)((t) % NBUF) * STG; \
    _Pragma("unroll") \
    for (int jl = 0; jl < 2; jl++) { \
        int jg = nw * 2 + jl; \
        uint32_t* Ah = ph + jl * 4; \
        uint32_t coff = (uint32_t)(((2 * jg + lcb) ^ lsw) * 16); \
        _Pragma("unroll") \
        for (int np = 0; np < 2; np++) { \
            uint32_t va[4], vb[4]; \
            LDSM4(va, kb + 8192 + (uint32_t)(2 * np) * 2048 + lro + coff); \
            LDSM4(vb, kb + 8192 + (uint32_t)(2 * np + 1) * 2048 + lro + coff); \
            MMAH(o[4*np],     Ah, va[0], va[1]); \
            MMAH(o[4*np + 2], Ah, vb[0], vb[1]); \
            MMAH(o[4*np + 1], Ah, va[2], va[3]); \
            MMAH(o[4*np + 3], Ah, vb[2], vb[3]); \
        } \
    } \
} while (0)

// PV(t) interleaved with QK(t+1)->c (c dead before entry; reused)
#define PVQK_TILE(t) do { \
    uint32_t kbV = sb + (uint32_t)((t) % NBUF) * STG; \
    uint32_t kbK = sb + (uint32_t)(((t) + 1) % NBUF) * STG; \
    _Pragma("unroll") \
    for (int i = 0; i < 4; i++) c[i][0] = c[i][1] = c[i][2] = c[i][3] = 0.f; \
    _Pragma("unroll") \
    for (int kk = 0; kk < 4; kk++) { \
        int jl = kk >> 1, np = kk & 1; \
        int jg = nw * 2 + jl; \
        uint32_t coffV = (uint32_t)(((2 * jg + lcb) ^ lsw) * 16); \
        uint32_t coffK = (uint32_t)(((2 * kk + lcb) ^ lsw) * 16); \
        uint32_t va[4], vb[4], bh0[4], bh1[4]; \
        LDSM4(va, kbV + 8192 + (uint32_t)(2 * np) * 2048 + lro + coffV); \
        LDSM4(vb, kbV + 8192 + (uint32_t)(2 * np + 1) * 2048 + lro + coffV); \
        LDSM4(bh0, kbK + (uint32_t)(nw * 2 + 0) * 2048 + lro + coffK); \
        LDSM4(bh1, kbK + (uint32_t)(nw * 2 + 1) * 2048 + lro + coffK); \
        uint32_t* Ah = ph + jl * 4; \
        MMAH(c[0], qh[kk], bh0[0], bh0[1]); \
        MMAH(o[4*np],     Ah, va[0], va[1]); \
        MMAH(c[2], qh[kk], bh1[0], bh1[1]); \
        MMAH(o[4*np + 2], Ah, vb[0], vb[1]); \
        MMAH(c[1], qh[kk], bh0[2], bh0[3]); \
        MMAH(o[4*np + 1], Ah, va[2], va[3]); \
        MMAH(c[3], qh[kk], bh1[2], bh1[3]); \
        MMAH(o[4*np + 3], Ah, vb[2], vb[3]); \
        MMAH(c[0], ql[kk], bh0[0], bh0[1]); \
        MMAH(c[2], ql[kk], bh1[0], bh1[1]); \
        MMAH(c[1], ql[kk], bh0[2], bh0[3]); \
        MMAH(c[3], ql[kk], bh1[2], bh1[3]); \
    } \
} while (0)

    for (int tt = 0; tt < NT; tt += 2) {
        if (tt >= NT - 2) { asm volatile("cp.async.wait_group 0;"); }
        else              { asm volatile("cp.async.wait_group 2;"); }
        __syncthreads();   // publish tiles tt,tt+1; all warps done with <= tt-1
        if (tt + 4 < NT) LOAD_TILE(tt + 4, (tt + 4) % NBUF);
        if (tt + 5 < NT) LOAD_TILE(tt + 5, (tt + 5) % NBUF);

        QK_TILE(tt);
        SOFTMAX_TILE();
        PVQK_TILE(tt);        // PV(tt) || QK(tt+1) -> c
        SOFTMAX_TILE();
        PV_TILE(tt + 1);
    }

    // ---- epilogue: store partials (slot = h*2 + nw) ----
    int slot = h * 2 + nw;
    {
        float l0 = lacc[0], l1 = lacc[1];
        l0 += __shfl_xor_sync(0xffffffffu, l0, 1);
        l0 += __shfl_xor_sync(0xffffffffu, l0, 2);
        l1 += __shfl_xor_sync(0xffffffffu, l1, 1);
        l1 += __shfl_xor_sync(0xffffffffu, l1, 2);
        int mg = q0 + mw * 16 + (L >> 2);
        float* op = g_Opart[slot] + ((size_t)b * HW + mg) * CKD;
        #pragma unroll
        for (int vt = 0; vt < 8; vt++) {
            int v = vt * 8 + (L & 3) * 2;
            *(float2*)(op + v)           = make_float2(o[vt][0], o[vt][1]);
            *(float2*)(op + 8 * CKD + v) = make_float2(o[vt][2], o[vt][3]);
        }
        if ((L & 3) == 0) {
            g_Lpart[slot][(size_t)b * HW + mg]     = l0;
            g_Lpart[slot][(size_t)b * HW + mg + 8] = l1;
            g_Mpart[slot][(size_t)b * HW + mg]     = mrow[0];
            g_Mpart[slot][(size_t)b * HW + mg + 8] = mrow[1];
        }
    }
}

// ---- combine: FA split-k merge, 512 blocks x 16 rows ----
__global__ void combine_kernel(float* __restrict__ out) {
    __shared__ float st[16][65];
    int g0 = blockIdx.x * 16;
    int tid = threadIdx.x;
    int b = g0 >> 12;
    {
        int r = tid >> 4, v4 = (tid & 15) * 4;
        int row = g0 + r;
        float m0 = g_Mpart[0][row], m1 = g_Mpart[1][row];
        float m2 = g_Mpart[2][row], m3 = g_Mpart[3][row];
        float ms = fmaxf(fmaxf(m0, m1), fmaxf(m2, m3));
        float w0 = ex2f(m0 - ms), w1 = ex2f(m1 - ms);
        float w2 = ex2f(m2 - ms), w3 = ex2f(m3 - ms);
        float lsum = w0 * g_Lpart[0][row] + w1 * g_Lpart[1][row]
                   + w2 * g_Lpart[2][row] + w3 * g_Lpart[3][row];
        float inv = 1.0f / lsum;
        size_t idx = (size_t)row * CKD + v4;
        float4 a0 = *(const float4*)(g_Opart[0] + idx);
        float4 a1 = *(const float4*)(g_Opart[1] + idx);
        float4 a2 = *(const float4*)(g_Opart[2] + idx);
        float4 a3 = *(const float4*)(g_Opart[3] + idx);
        st[r][v4]   = (w0*a0.x + w1*a1.x + w2*a2.x + w3*a3.x) * inv;
        st[r][v4+1] = (w0*a0.y + w1*a1.y + w2*a2.y + w3*a3.y) * inv;
        st[r][v4+2] = (w0*a0.z + w1*a1.z + w2*a2.z + w3*a3.z) * inv;
        st[r][v4+3] = (w0*a0.w + w1*a1.w + w2*a2.w + w3*a3.w) * inv;
    }
    __syncthreads();
    float* ob = out + (size_t)b * CKD * HW;
    int qb = g0 & 4095;
    {
        int v = tid >> 2, r4 = (tid & 3) * 4;
        float mval = g_maskV[b][v];
        float4 w;
        w.x = st[r4][v]   + mval;
        w.y = st[r4+1][v] + mval;
        w.z = st[r4+2][v] + mval;
        w.w = st[r4+3][v] + mval;
        *(float4*)(ob + (size_t)v * HW + qb + r4) = w;
    }
}

// ---- launch ----
extern "C" void kernel_launch(void* const* d_in, const int* in_sizes, int n_in,
                              void* d_out, int out_size) {
    const float* mk   = (const float*)d_in[0];
    const float* mv   = (const float*)d_in[1];
    const float* qq   = (const float*)d_in[2];
    const float* disp = (const float*)d_in[3];
    const int*   seq  = (const int*)d_in[4];
    float* out = (float*)d_out;

    kqtrans_kernel<<<576, TPB>>>(mk, qq);
    vconv_kernel<<<4096, TPB>>>(mv, disp, seq);

    cudaFuncSetAttribute(attn_mma_kernel, cudaFuncAttributeMaxDynamicSharedMemorySize, SMEM_TOTAL);
    attn_mma_kernel<<<128, ATPB, SMEM_TOTAL>>>();

    combine_kernel<<<512, TPB>>>(out);
}